// round 1
// baseline (speedup 1.0000x reference)
#include <cuda_runtime.h>

#define B_  2
#define S_  2048
#define D_  1024
#define H_  16
#define DK_ 64

// Scratch (allocation-free rule: __device__ globals)
__device__ float g_Q[B_ * S_ * D_];
__device__ float g_K[B_ * S_ * D_];
__device__ float g_V[B_ * S_ * D_];
__device__ float g_C[B_ * S_ * D_];

// ---------------------------------------------------------------------------
// Projection GEMM: out[m,n] = sum_k X[m,k] * W[n,k] + bias[n]
// (torch Linear: x @ W^T + b). BM=BN=64, BK=16, 256 threads, 4x4 per thread.
// Shared tiles stored transposed [k][m] so compute reads are LDS.128,
// conflict-free (rows padded to 68 floats = 16B-aligned, non-pow2 bank stride).
// ---------------------------------------------------------------------------
__global__ void __launch_bounds__(256)
proj_kernel(const float* __restrict__ X, const float* __restrict__ W,
            const float* __restrict__ bias, float* __restrict__ out,
            int M, int N, int K)
{
    __shared__ __align__(16) float Xs[16][68];
    __shared__ __align__(16) float Ws[16][68];

    const int t  = threadIdx.x;
    const int tx = t & 15;
    const int ty = t >> 4;
    const int bm = blockIdx.y * 64;
    const int bn = blockIdx.x * 64;

    const int lrow = t >> 2;          // 0..63
    const int lc4  = (t & 3) << 2;    // 0,4,8,12

    float acc[4][4] = {};

    for (int k0 = 0; k0 < K; k0 += 16) {
        float4 xv = *(const float4*)&X[(size_t)(bm + lrow) * K + k0 + lc4];
        float4 wv = *(const float4*)&W[(size_t)(bn + lrow) * K + k0 + lc4];
        Xs[lc4 + 0][lrow] = xv.x; Xs[lc4 + 1][lrow] = xv.y;
        Xs[lc4 + 2][lrow] = xv.z; Xs[lc4 + 3][lrow] = xv.w;
        Ws[lc4 + 0][lrow] = wv.x; Ws[lc4 + 1][lrow] = wv.y;
        Ws[lc4 + 2][lrow] = wv.z; Ws[lc4 + 3][lrow] = wv.w;
        __syncthreads();

        #pragma unroll
        for (int kk = 0; kk < 16; kk++) {
            float4 a = *(const float4*)&Xs[kk][ty * 4];
            float4 b = *(const float4*)&Ws[kk][tx * 4];
            float av[4] = {a.x, a.y, a.z, a.w};
            float bv[4] = {b.x, b.y, b.z, b.w};
            #pragma unroll
            for (int i = 0; i < 4; i++)
                #pragma unroll
                for (int j = 0; j < 4; j++)
                    acc[i][j] = fmaf(av[i], bv[j], acc[i][j]);
        }
        __syncthreads();
    }

    float4 bb = *(const float4*)&bias[bn + tx * 4];
    #pragma unroll
    for (int i = 0; i < 4; i++) {
        int m = bm + ty * 4 + i;
        float4 r = make_float4(acc[i][0] + bb.x, acc[i][1] + bb.y,
                               acc[i][2] + bb.z, acc[i][3] + bb.w);
        *(float4*)&out[(size_t)m * N + bn + tx * 4] = r;
    }
}

// ---------------------------------------------------------------------------
// Flash attention: one block per (b, h, 64-query tile). 256 threads (16x16),
// 4x4 register tiles for both S = Q K^T and O += P V. Online softmax with
// 16-lane shfl reductions (row owned by the 16 tx-lanes of each ty group).
// Q/K stored transposed [d][token] in smem; P stored transposed [k][q];
// V stored natural [k][d] — all inner-loop reads are conflict-free LDS.128.
// ---------------------------------------------------------------------------
__global__ void __launch_bounds__(256)
attn_kernel(const float* __restrict__ Q, const float* __restrict__ K,
            const float* __restrict__ V, const int* __restrict__ mask,
            float* __restrict__ ctx)
{
    extern __shared__ __align__(16) float smem[];
    float (*QsT)[68] = (float (*)[68])(smem);
    float (*KsT)[68] = (float (*)[68])(smem + 64 * 68);
    float (*Vs )[68] = (float (*)[68])(smem + 2 * 64 * 68);
    float (*PsT)[68] = (float (*)[68])(smem + 3 * 64 * 68);

    const int t  = threadIdx.x;
    const int tx = t & 15;
    const int ty = t >> 4;
    const int b  = blockIdx.z;
    const int h  = blockIdx.y;
    const int q0 = blockIdx.x * 64;
    const float scale = 0.125f;  // 1/sqrt(64)

    // Load Q tile transposed (scale folded in)
    #pragma unroll
    for (int it = 0; it < 4; it++) {
        int flat = t + it * 256;
        int row  = flat >> 4;
        int c4   = (flat & 15) << 2;
        float4 v = *(const float4*)&Q[(size_t)(b * S_ + q0 + row) * D_ + h * DK_ + c4];
        QsT[c4 + 0][row] = v.x * scale; QsT[c4 + 1][row] = v.y * scale;
        QsT[c4 + 2][row] = v.z * scale; QsT[c4 + 3][row] = v.w * scale;
    }

    float m_i[4], l_i[4], o[4][4];
    #pragma unroll
    for (int i = 0; i < 4; i++) {
        m_i[i] = -1e30f; l_i[i] = 0.f;
        #pragma unroll
        for (int j = 0; j < 4; j++) o[i][j] = 0.f;
    }

    for (int k0 = 0; k0 < S_; k0 += 64) {
        // Load K (transposed) and V (natural) tiles
        #pragma unroll
        for (int it = 0; it < 4; it++) {
            int flat = t + it * 256;
            int row  = flat >> 4;
            int c4   = (flat & 15) << 2;
            float4 kv = *(const float4*)&K[(size_t)(b * S_ + k0 + row) * D_ + h * DK_ + c4];
            KsT[c4 + 0][row] = kv.x; KsT[c4 + 1][row] = kv.y;
            KsT[c4 + 2][row] = kv.z; KsT[c4 + 3][row] = kv.w;
            float4 vv = *(const float4*)&V[(size_t)(b * S_ + k0 + row) * D_ + h * DK_ + c4];
            *(float4*)&Vs[row][c4] = vv;
        }
        __syncthreads();

        // S = (Q*scale) K^T
        float s[4][4] = {};
        #pragma unroll 8
        for (int d = 0; d < 64; d++) {
            float4 a  = *(const float4*)&QsT[d][ty * 4];
            float4 bb = *(const float4*)&KsT[d][tx * 4];
            float av[4] = {a.x, a.y, a.z, a.w};
            float bv[4] = {bb.x, bb.y, bb.z, bb.w};
            #pragma unroll
            for (int i = 0; i < 4; i++)
                #pragma unroll
                for (int j = 0; j < 4; j++)
                    s[i][j] = fmaf(av[i], bv[j], s[i][j]);
        }

        // Mask (all-ones in this dataset; honored anyway, L2-resident)
        const int* mrow = mask + (size_t)(q0 + ty * 4) * S_ + k0 + tx * 4;
        #pragma unroll
        for (int i = 0; i < 4; i++)
            #pragma unroll
            for (int j = 0; j < 4; j++)
                if (mrow[(size_t)i * S_ + j] == 0) s[i][j] = -1e9f;

        // Online softmax per row; stage P transposed into smem
        #pragma unroll
        for (int i = 0; i < 4; i++) {
            float rm = fmaxf(fmaxf(s[i][0], s[i][1]), fmaxf(s[i][2], s[i][3]));
            for (int off = 8; off >= 1; off >>= 1)
                rm = fmaxf(rm, __shfl_xor_sync(0xffffffffu, rm, off));
            float mnew  = fmaxf(m_i[i], rm);
            float alpha = __expf(m_i[i] - mnew);
            float rs = 0.f;
            #pragma unroll
            for (int j = 0; j < 4; j++) {
                float p = __expf(s[i][j] - mnew);
                s[i][j] = p;
                rs += p;
            }
            for (int off = 8; off >= 1; off >>= 1)
                rs += __shfl_xor_sync(0xffffffffu, rs, off);
            l_i[i] = l_i[i] * alpha + rs;
            m_i[i] = mnew;
            #pragma unroll
            for (int j = 0; j < 4; j++) o[i][j] *= alpha;
            #pragma unroll
            for (int j = 0; j < 4; j++) PsT[tx * 4 + j][ty * 4 + i] = s[i][j];
        }
        __syncthreads();

        // O += P V
        #pragma unroll 8
        for (int kk = 0; kk < 64; kk++) {
            float4 p  = *(const float4*)&PsT[kk][ty * 4];
            float4 vv = *(const float4*)&Vs[kk][tx * 4];
            float pv[4] = {p.x, p.y, p.z, p.w};
            float vw[4] = {vv.x, vv.y, vv.z, vv.w};
            #pragma unroll
            for (int i = 0; i < 4; i++)
                #pragma unroll
                for (int j = 0; j < 4; j++)
                    o[i][j] = fmaf(pv[i], vw[j], o[i][j]);
        }
        __syncthreads();
    }

    // Normalize and write context in [B,S,D] (head-interleaved) layout
    #pragma unroll
    for (int i = 0; i < 4; i++) {
        float inv = 1.f / l_i[i];
        float4 r = make_float4(o[i][0] * inv, o[i][1] * inv,
                               o[i][2] * inv, o[i][3] * inv);
        *(float4*)&ctx[(size_t)(b * S_ + q0 + ty * 4 + i) * D_ + h * DK_ + tx * 4] = r;
    }
}

// ---------------------------------------------------------------------------
extern "C" void kernel_launch(void* const* d_in, const int* in_sizes, int n_in,
                              void* d_out, int out_size)
{
    const float* q    = (const float*)d_in[0];
    const float* k    = (const float*)d_in[1];
    const float* v    = (const float*)d_in[2];
    const int*   mask = (const int*)  d_in[3];
    const float* Wq   = (const float*)d_in[4];
    const float* bq   = (const float*)d_in[5];
    const float* Wk   = (const float*)d_in[6];
    const float* bk   = (const float*)d_in[7];
    const float* Wv   = (const float*)d_in[8];
    const float* bv   = (const float*)d_in[9];
    const float* Wo   = (const float*)d_in[10];
    const float* bo   = (const float*)d_in[11];
    float* out = (float*)d_out;

    float *Qp, *Kp, *Vp, *Cp;
    cudaGetSymbolAddress((void**)&Qp, g_Q);
    cudaGetSymbolAddress((void**)&Kp, g_K);
    cudaGetSymbolAddress((void**)&Vp, g_V);
    cudaGetSymbolAddress((void**)&Cp, g_C);

    const int M = B_ * S_;
    dim3 pgrid(D_ / 64, M / 64);

    proj_kernel<<<pgrid, 256>>>(q, Wq, bq, Qp, M, D_, D_);
    proj_kernel<<<pgrid, 256>>>(k, Wk, bk, Kp, M, D_, D_);
    proj_kernel<<<pgrid, 256>>>(v, Wv, bv, Vp, M, D_, D_);

    const int attn_smem = 4 * 64 * 68 * (int)sizeof(float);  // 69632 B
    cudaFuncSetAttribute(attn_kernel,
                         cudaFuncAttributeMaxDynamicSharedMemorySize, attn_smem);
    attn_kernel<<<dim3(S_ / 64, H_, B_), 256, attn_smem>>>(Qp, Kp, Vp, mask, Cp);

    proj_kernel<<<pgrid, 256>>>(Cp, Wo, bo, out, M, D_, D_);
}

// round 2
// speedup vs baseline: 1.0012x; 1.0012x over previous
#include <cuda_runtime.h>

#define B_  2
#define S_  2048
#define D_  1024
#define H_  16
#define DK_ 64

// Scratch (allocation-free rule: __device__ globals)
__device__ float g_Q[B_ * S_ * D_];
__device__ float g_K[B_ * S_ * D_];
__device__ float g_V[B_ * S_ * D_];
__device__ float g_C[B_ * S_ * D_];

// ---------------------------------------------------------------------------
// Projection GEMM: out[m,n] = sum_k X[m,k] * W[n,k] + bias[n]
// (torch Linear: x @ W^T + b). BM=BN=64, BK=16, 256 threads, 4x4 per thread.
// Shared tiles stored transposed [k][m] so compute reads are LDS.128,
// conflict-free (rows padded to 68 floats = 16B-aligned, non-pow2 bank stride).
// ---------------------------------------------------------------------------
__global__ void __launch_bounds__(256)
proj_kernel(const float* __restrict__ X, const float* __restrict__ W,
            const float* __restrict__ bias, float* __restrict__ out,
            int M, int N, int K)
{
    __shared__ __align__(16) float Xs[16][68];
    __shared__ __align__(16) float Ws[16][68];

    const int t  = threadIdx.x;
    const int tx = t & 15;
    const int ty = t >> 4;
    const int bm = blockIdx.y * 64;
    const int bn = blockIdx.x * 64;

    const int lrow = t >> 2;          // 0..63
    const int lc4  = (t & 3) << 2;    // 0,4,8,12

    float acc[4][4] = {};

    for (int k0 = 0; k0 < K; k0 += 16) {
        float4 xv = *(const float4*)&X[(size_t)(bm + lrow) * K + k0 + lc4];
        float4 wv = *(const float4*)&W[(size_t)(bn + lrow) * K + k0 + lc4];
        Xs[lc4 + 0][lrow] = xv.x; Xs[lc4 + 1][lrow] = xv.y;
        Xs[lc4 + 2][lrow] = xv.z; Xs[lc4 + 3][lrow] = xv.w;
        Ws[lc4 + 0][lrow] = wv.x; Ws[lc4 + 1][lrow] = wv.y;
        Ws[lc4 + 2][lrow] = wv.z; Ws[lc4 + 3][lrow] = wv.w;
        __syncthreads();

        #pragma unroll
        for (int kk = 0; kk < 16; kk++) {
            float4 a = *(const float4*)&Xs[kk][ty * 4];
            float4 b = *(const float4*)&Ws[kk][tx * 4];
            float av[4] = {a.x, a.y, a.z, a.w};
            float bv[4] = {b.x, b.y, b.z, b.w};
            #pragma unroll
            for (int i = 0; i < 4; i++)
                #pragma unroll
                for (int j = 0; j < 4; j++)
                    acc[i][j] = fmaf(av[i], bv[j], acc[i][j]);
        }
        __syncthreads();
    }

    float4 bb = *(const float4*)&bias[bn + tx * 4];
    #pragma unroll
    for (int i = 0; i < 4; i++) {
        int m = bm + ty * 4 + i;
        float4 r = make_float4(acc[i][0] + bb.x, acc[i][1] + bb.y,
                               acc[i][2] + bb.z, acc[i][3] + bb.w);
        *(float4*)&out[(size_t)m * N + bn + tx * 4] = r;
    }
}

// ---------------------------------------------------------------------------
// Flash attention: one block per (b, h, 64-query tile). 256 threads (16x16),
// 4x4 register tiles for both S = Q K^T and O += P V. Online softmax with
// 16-lane shfl reductions (row owned by the 16 tx-lanes of each ty group).
// Q/K stored transposed [d][token] in smem; P stored transposed [k][q];
// V stored natural [k][d] — all inner-loop reads are conflict-free LDS.128.
// ---------------------------------------------------------------------------
__global__ void __launch_bounds__(256)
attn_kernel(const float* __restrict__ Q, const float* __restrict__ K,
            const float* __restrict__ V, const int* __restrict__ mask,
            float* __restrict__ ctx)
{
    extern __shared__ __align__(16) float smem[];
    float (*QsT)[68] = (float (*)[68])(smem);
    float (*KsT)[68] = (float (*)[68])(smem + 64 * 68);
    float (*Vs )[68] = (float (*)[68])(smem + 2 * 64 * 68);
    float (*PsT)[68] = (float (*)[68])(smem + 3 * 64 * 68);

    const int t  = threadIdx.x;
    const int tx = t & 15;
    const int ty = t >> 4;
    const int b  = blockIdx.z;
    const int h  = blockIdx.y;
    const int q0 = blockIdx.x * 64;
    const float scale = 0.125f;  // 1/sqrt(64)

    // Load Q tile transposed (scale folded in)
    #pragma unroll
    for (int it = 0; it < 4; it++) {
        int flat = t + it * 256;
        int row  = flat >> 4;
        int c4   = (flat & 15) << 2;
        float4 v = *(const float4*)&Q[(size_t)(b * S_ + q0 + row) * D_ + h * DK_ + c4];
        QsT[c4 + 0][row] = v.x * scale; QsT[c4 + 1][row] = v.y * scale;
        QsT[c4 + 2][row] = v.z * scale; QsT[c4 + 3][row] = v.w * scale;
    }

    float m_i[4], l_i[4], o[4][4];
    #pragma unroll
    for (int i = 0; i < 4; i++) {
        m_i[i] = -1e30f; l_i[i] = 0.f;
        #pragma unroll
        for (int j = 0; j < 4; j++) o[i][j] = 0.f;
    }

    for (int k0 = 0; k0 < S_; k0 += 64) {
        // Load K (transposed) and V (natural) tiles
        #pragma unroll
        for (int it = 0; it < 4; it++) {
            int flat = t + it * 256;
            int row  = flat >> 4;
            int c4   = (flat & 15) << 2;
            float4 kv = *(const float4*)&K[(size_t)(b * S_ + k0 + row) * D_ + h * DK_ + c4];
            KsT[c4 + 0][row] = kv.x; KsT[c4 + 1][row] = kv.y;
            KsT[c4 + 2][row] = kv.z; KsT[c4 + 3][row] = kv.w;
            float4 vv = *(const float4*)&V[(size_t)(b * S_ + k0 + row) * D_ + h * DK_ + c4];
            *(float4*)&Vs[row][c4] = vv;
        }
        __syncthreads();

        // S = (Q*scale) K^T
        float s[4][4] = {};
        #pragma unroll 8
        for (int d = 0; d < 64; d++) {
            float4 a  = *(const float4*)&QsT[d][ty * 4];
            float4 bb = *(const float4*)&KsT[d][tx * 4];
            float av[4] = {a.x, a.y, a.z, a.w};
            float bv[4] = {bb.x, bb.y, bb.z, bb.w};
            #pragma unroll
            for (int i = 0; i < 4; i++)
                #pragma unroll
                for (int j = 0; j < 4; j++)
                    s[i][j] = fmaf(av[i], bv[j], s[i][j]);
        }

        // Mask (all-ones in this dataset; honored anyway, L2-resident)
        const int* mrow = mask + (size_t)(q0 + ty * 4) * S_ + k0 + tx * 4;
        #pragma unroll
        for (int i = 0; i < 4; i++)
            #pragma unroll
            for (int j = 0; j < 4; j++)
                if (mrow[(size_t)i * S_ + j] == 0) s[i][j] = -1e9f;

        // Online softmax per row; stage P transposed into smem
        #pragma unroll
        for (int i = 0; i < 4; i++) {
            float rm = fmaxf(fmaxf(s[i][0], s[i][1]), fmaxf(s[i][2], s[i][3]));
            for (int off = 8; off >= 1; off >>= 1)
                rm = fmaxf(rm, __shfl_xor_sync(0xffffffffu, rm, off));
            float mnew  = fmaxf(m_i[i], rm);
            float alpha = __expf(m_i[i] - mnew);
            float rs = 0.f;
            #pragma unroll
            for (int j = 0; j < 4; j++) {
                float p = __expf(s[i][j] - mnew);
                s[i][j] = p;
                rs += p;
            }
            for (int off = 8; off >= 1; off >>= 1)
                rs += __shfl_xor_sync(0xffffffffu, rs, off);
            l_i[i] = l_i[i] * alpha + rs;
            m_i[i] = mnew;
            #pragma unroll
            for (int j = 0; j < 4; j++) o[i][j] *= alpha;
            #pragma unroll
            for (int j = 0; j < 4; j++) PsT[tx * 4 + j][ty * 4 + i] = s[i][j];
        }
        __syncthreads();

        // O += P V
        #pragma unroll 8
        for (int kk = 0; kk < 64; kk++) {
            float4 p  = *(const float4*)&PsT[kk][ty * 4];
            float4 vv = *(const float4*)&Vs[kk][tx * 4];
            float pv[4] = {p.x, p.y, p.z, p.w};
            float vw[4] = {vv.x, vv.y, vv.z, vv.w};
            #pragma unroll
            for (int i = 0; i < 4; i++)
                #pragma unroll
                for (int j = 0; j < 4; j++)
                    o[i][j] = fmaf(pv[i], vw[j], o[i][j]);
        }
        __syncthreads();
    }

    // Normalize and write context in [B,S,D] (head-interleaved) layout
    #pragma unroll
    for (int i = 0; i < 4; i++) {
        float inv = 1.f / l_i[i];
        float4 r = make_float4(o[i][0] * inv, o[i][1] * inv,
                               o[i][2] * inv, o[i][3] * inv);
        *(float4*)&ctx[(size_t)(b * S_ + q0 + ty * 4 + i) * D_ + h * DK_ + tx * 4] = r;
    }
}

// ---------------------------------------------------------------------------
extern "C" void kernel_launch(void* const* d_in, const int* in_sizes, int n_in,
                              void* d_out, int out_size)
{
    const float* q    = (const float*)d_in[0];
    const float* k    = (const float*)d_in[1];
    const float* v    = (const float*)d_in[2];
    const int*   mask = (const int*)  d_in[3];
    const float* Wq   = (const float*)d_in[4];
    const float* bq   = (const float*)d_in[5];
    const float* Wk   = (const float*)d_in[6];
    const float* bk   = (const float*)d_in[7];
    const float* Wv   = (const float*)d_in[8];
    const float* bv   = (const float*)d_in[9];
    const float* Wo   = (const float*)d_in[10];
    const float* bo   = (const float*)d_in[11];
    float* out = (float*)d_out;

    float *Qp, *Kp, *Vp, *Cp;
    cudaGetSymbolAddress((void**)&Qp, g_Q);
    cudaGetSymbolAddress((void**)&Kp, g_K);
    cudaGetSymbolAddress((void**)&Vp, g_V);
    cudaGetSymbolAddress((void**)&Cp, g_C);

    const int M = B_ * S_;
    dim3 pgrid(D_ / 64, M / 64);

    proj_kernel<<<pgrid, 256>>>(q, Wq, bq, Qp, M, D_, D_);
    proj_kernel<<<pgrid, 256>>>(k, Wk, bk, Kp, M, D_, D_);
    proj_kernel<<<pgrid, 256>>>(v, Wv, bv, Vp, M, D_, D_);

    const int attn_smem = 4 * 64 * 68 * (int)sizeof(float);  // 69632 B
    cudaFuncSetAttribute(attn_kernel,
                         cudaFuncAttributeMaxDynamicSharedMemorySize, attn_smem);
    attn_kernel<<<dim3(S_ / 64, H_, B_), 256, attn_smem>>>(Qp, Kp, Vp, mask, Cp);

    proj_kernel<<<pgrid, 256>>>(Cp, Wo, bo, out, M, D_, D_);
}